// round 2
// baseline (speedup 1.0000x reference)
#include <cuda_runtime.h>

// ============================================================================
// SRU cell. L=2048, B=16, D=1024.
//   u = x @ W   (32768 x 1024) @ (1024 x 3072)  -> tf32 mma.sync GEMM (legacy
//                                                  tensor path; tcgen05 is an
//                                                  'a'-feature and the harness
//                                                  compiles PTX at compute_103)
//   sequential scan over L on 16384 channels    -> scan kernel
// ============================================================================

#define L_DIM 2048
#define B_DIM 16
#define D_DIM 1024
#define N_DIM 3072
#define K_DIM 1024
#define M_DIM 32768  // L*B

#define BM 128
#define BN 128
#define BK 32
#define STAGES 3
#define ROWSTR 36           // BK + 4 floats pad: conflict-free frag loads
#define KT (K_DIM / BK)     // 32
#define GEMM_SMEM_BYTES (STAGES * 2 * BM * ROWSTR * 4)   // 110592

// Scratch (allocation-free rule: __device__ globals)
__device__ float g_Wt[N_DIM * K_DIM];          // W transposed + tf32-rounded (12 MB)
__device__ float g_U[(size_t)M_DIM * N_DIM];   // GEMM output u (402 MB)

// ---------------------------------------------------------------------------
__device__ __forceinline__ unsigned smem_u32(const void* p) {
    unsigned a;
    asm("{ .reg .u64 t; cvta.to.shared.u64 t, %1; cvt.u32.u64 %0, t; }" : "=r"(a) : "l"(p));
    return a;
}

__device__ __forceinline__ unsigned f2tf32(float x) {
    unsigned u;
    asm("cvt.rna.tf32.f32 %0, %1;" : "=r"(u) : "f"(x));
    return u;
}

__device__ __forceinline__ void cp_async16(unsigned dst, const void* src) {
    asm volatile("cp.async.cg.shared.global [%0], [%1], 16;" :: "r"(dst), "l"(src));
}

__device__ __forceinline__ void mma_tf32(float* c, const unsigned* a, const unsigned* b) {
    asm volatile(
        "mma.sync.aligned.m16n8k8.row.col.f32.tf32.tf32.f32 "
        "{%0,%1,%2,%3}, {%4,%5,%6,%7}, {%8,%9}, {%0,%1,%2,%3};"
        : "+f"(c[0]), "+f"(c[1]), "+f"(c[2]), "+f"(c[3])
        : "r"(a[0]), "r"(a[1]), "r"(a[2]), "r"(a[3]), "r"(b[0]), "r"(b[1]));
}

// ---------------------------------------------------------------------------
// Kernel 1: transpose + tf32-round W (K,N) -> Wt (N,K)
// ---------------------------------------------------------------------------
__global__ void transpose_w(const float* __restrict__ W) {
    __shared__ float t[32][33];
    int n0 = blockIdx.x * 32, k0 = blockIdx.y * 32;
    int tx = threadIdx.x, ty = threadIdx.y;  // 32 x 8
#pragma unroll
    for (int i = 0; i < 32; i += 8)
        t[ty + i][tx] = W[(size_t)(k0 + ty + i) * N_DIM + n0 + tx];
    __syncthreads();
#pragma unroll
    for (int i = 0; i < 32; i += 8) {
        unsigned u = f2tf32(t[tx][ty + i]);
        g_Wt[(size_t)(n0 + ty + i) * K_DIM + k0 + tx] = __uint_as_float(u);
    }
}

// ---------------------------------------------------------------------------
// Kernel 2: tf32 mma.sync GEMM. CTA 128x128, BK=32, 3-stage cp.async pipeline.
// 8 warps: 4(M) x 2(N); warp tile 32(M) x 64(N); mma m16n8k8.
// ---------------------------------------------------------------------------
__global__ void __launch_bounds__(256, 2) gemm_tf32(const float* __restrict__ X) {
    extern __shared__ float smem_f[];
    unsigned sbase = smem_u32(smem_f);

    int tid = threadIdx.x;
    int wid = tid >> 5;
    int lid = tid & 31;
    int g   = lid >> 2;     // group id 0..7
    int t4  = lid & 3;      // 0..3
    int warp_m = wid >> 1;  // 0..3
    int warp_n = wid & 1;   // 0..1
    int mbase = warp_m * 32;
    int nbase = warp_n * 64;

    int n0 = blockIdx.x * BN;
    int m0 = blockIdx.y * BM;

    const float* Arow = X + (size_t)m0 * K_DIM;
    const float* Brow = g_Wt + (size_t)n0 * K_DIM;

    const int STAGE_F = 2 * BM * ROWSTR;         // floats per stage (A+B)
    const int B_OFF_F = BM * ROWSTR;             // B offset within stage

    float acc[2][8][4];
#pragma unroll
    for (int mt = 0; mt < 2; mt++)
#pragma unroll
        for (int nt = 0; nt < 8; nt++)
#pragma unroll
            for (int i = 0; i < 4; i++) acc[mt][nt][i] = 0.0f;

    // ---- issue loads for one stage (4 A + 4 B float4 per thread) ----
    auto load_stage = [&](int stage, int kc) {
        unsigned sA = sbase + (unsigned)(stage * STAGE_F) * 4u;
        unsigned sB = sA + (unsigned)B_OFF_F * 4u;
#pragma unroll
        for (int t = 0; t < 4; t++) {
            int j = tid + t * 256;          // 0..1023
            int row = j >> 3;               // 0..127
            int c4 = j & 7;                 // float4 index within 32-float row
            unsigned off = (unsigned)(row * ROWSTR + c4 * 4) * 4u;
            cp_async16(sA + off, Arow + (size_t)row * K_DIM + kc + c4 * 4);
            cp_async16(sB + off, Brow + (size_t)row * K_DIM + kc + c4 * 4);
        }
        asm volatile("cp.async.commit_group;" ::: "memory");
    };

    // prefetch STAGES-1 stages
#pragma unroll
    for (int s = 0; s < STAGES - 1; s++) load_stage(s, s * BK);

    for (int kt = 0; kt < KT; kt++) {
        asm volatile("cp.async.wait_group %0;" :: "n"(STAGES - 2) : "memory");
        __syncthreads();

        // issue loads for stage kt+STAGES-1 (overlaps with compute below)
        if (kt + STAGES - 1 < KT)
            load_stage((kt + STAGES - 1) % STAGES, (kt + STAGES - 1) * BK);
        else
            asm volatile("cp.async.commit_group;" ::: "memory");  // keep group count

        const float* As = smem_f + (kt % STAGES) * STAGE_F;
        const float* Bs = As + B_OFF_F;

#pragma unroll
        for (int kk = 0; kk < 4; kk++) {
            int k = kk * 8 + t4;
            unsigned a[2][4];
#pragma unroll
            for (int mt = 0; mt < 2; mt++) {
                int m = mbase + mt * 16 + g;
                a[mt][0] = f2tf32(As[m * ROWSTR + k]);
                a[mt][1] = f2tf32(As[(m + 8) * ROWSTR + k]);
                a[mt][2] = f2tf32(As[m * ROWSTR + k + 4]);
                a[mt][3] = f2tf32(As[(m + 8) * ROWSTR + k + 4]);
            }
            unsigned b[8][2];
#pragma unroll
            for (int nt = 0; nt < 8; nt++) {
                int n = nbase + nt * 8 + g;
                b[nt][0] = __float_as_uint(Bs[n * ROWSTR + k]);      // pre-rounded
                b[nt][1] = __float_as_uint(Bs[n * ROWSTR + k + 4]);
            }
#pragma unroll
            for (int mt = 0; mt < 2; mt++)
#pragma unroll
                for (int nt = 0; nt < 8; nt++)
                    mma_tf32(acc[mt][nt], a[mt], b[nt]);
        }
        __syncthreads();
    }

    // ---- epilogue: write u ----
#pragma unroll
    for (int mt = 0; mt < 2; mt++) {
#pragma unroll
        for (int nt = 0; nt < 8; nt++) {
            int row = m0 + mbase + mt * 16 + g;
            int col = n0 + nbase + nt * 8 + 2 * t4;
            float2 v0 = make_float2(acc[mt][nt][0], acc[mt][nt][1]);
            float2 v1 = make_float2(acc[mt][nt][2], acc[mt][nt][3]);
            *(float2*)&g_U[(size_t)row * N_DIM + col] = v0;
            *(float2*)&g_U[(size_t)(row + 8) * N_DIM + col] = v1;
        }
    }
}

// ---------------------------------------------------------------------------
// Kernel 3: sequential SRU scan. One thread per (b,d) channel.
// ---------------------------------------------------------------------------
__global__ void __launch_bounds__(128) sru_scan(const float* __restrict__ X,
                                                const float* __restrict__ C0,
                                                const float* __restrict__ Wc,
                                                const float* __restrict__ Bias,
                                                float* __restrict__ Out,
                                                int write_c) {
    int ch = blockIdx.x * 128 + threadIdx.x;  // 0..16383
    int d = ch & (D_DIM - 1);

    float fw = Wc[d], rw = Wc[D_DIM + d];
    float fb = Bias[d], rb = Bias[D_DIM + d];
    float c = C0[ch];

    const float SC = 1.7320508075688772f;  // sqrt(1 + 2*e^0)
    const float* up = g_U + (size_t)(ch >> 10) * N_DIM + 3 * d;
    const float* xp = X + ch;
    float* hp = Out + ch;

#pragma unroll 4
    for (int l = 0; l < L_DIM; l++) {
        float u0 = up[0], u1 = up[1], u2 = up[2];
        float xv = xp[0] * SC;
        float z1 = fmaf(c, fw, u1 + fb);
        float z2 = fmaf(c, rw, u2 + rb);
        float f = 1.0f / (1.0f + __expf(-z1));
        float r = 1.0f / (1.0f + __expf(-z2));
        c = u0 + (c - u0) * f;
        hp[0] = xv + (c - xv) * r;
        up += B_DIM * N_DIM;
        xp += B_DIM * D_DIM;
        hp += B_DIM * D_DIM;
    }
    if (write_c) Out[(size_t)L_DIM * B_DIM * D_DIM + ch] = c;
}

// ---------------------------------------------------------------------------
extern "C" void kernel_launch(void* const* d_in, const int* in_sizes, int n_in,
                              void* d_out, int out_size) {
    const float* x    = (const float*)d_in[0];
    const float* c0   = (const float*)d_in[1];
    const float* w    = (const float*)d_in[2];
    const float* wc   = (const float*)d_in[3];
    const float* bias = (const float*)d_in[4];
    float* out = (float*)d_out;

    int write_c = (out_size >= L_DIM * B_DIM * D_DIM + B_DIM * D_DIM) ? 1 : 0;

    static int smem_set = 0;
    if (!smem_set) {
        cudaFuncSetAttribute(gemm_tf32, cudaFuncAttributeMaxDynamicSharedMemorySize,
                             GEMM_SMEM_BYTES);
        smem_set = 1;
    }

    transpose_w<<<dim3(N_DIM / 32, K_DIM / 32), dim3(32, 8)>>>(w);
    gemm_tf32<<<dim3(N_DIM / BN, M_DIM / BM), 256, GEMM_SMEM_BYTES>>>(x);
    sru_scan<<<(B_DIM * D_DIM) / 128, 128>>>(x, c0, wc, bias, out, write_c);
}